// round 3
// baseline (speedup 1.0000x reference)
#include <cuda_runtime.h>
#include <math.h>

#define H 8
#define NNODES 4096
#define D 64

// out[h,n,:] = beta_h * softmax(q_n·K^T/8 + adj[h,n,:]) @ V  with diagonal of the
// attention matrix overwritten by alpha_h before the @V:
//   out[h,n,:] = beta_h*(P@v)[n,:] + (alpha_h - beta_h*P[n,n]) * v[h,n,:]
// When beta_h == 0 this collapses exactly to out = alpha_h * v (softmax is finite,
// 0*finite == 0 in fp32), so we take a pure scaled-copy path per head.
__global__ void attn_adj_kernel(const float* __restrict__ q,
                                const float* __restrict__ k,
                                const float* __restrict__ v,
                                const float* __restrict__ adj,
                                const float* __restrict__ alpha,
                                const float* __restrict__ beta,
                                float* __restrict__ out) {
    const int n = blockIdx.x;
    const int h = blockIdx.y;
    const int d = threadIdx.x;  // 0..63

    const float a = alpha[h];
    const float b = beta[h];
    const long long base = ((long long)h * NNODES + n) * D;

    if (b == 0.0f) {
        // Exact: out = alpha * v. Coalesced 256B per block.
        out[base + d] = a * v[base + d];
        return;
    }

    // ---- general path: online-softmax over the row (never runs when beta==0) ----
    __shared__ float qs[D];
    __shared__ float ebuf[64];
    __shared__ float red[64];
    __shared__ float pe_sh;  // e-value at the diagonal position for current chunk

    qs[d] = q[base + d];
    if (d == 0) pe_sh = 0.0f;
    __syncthreads();

    const float* kh = k + (long long)h * NNODES * D;
    const float* vh = v + (long long)h * NNODES * D;
    const float* adjrow = adj + ((long long)h * NNODES + n) * NNODES;

    float m_run = -INFINITY;
    float l_run = 0.0f;
    float acc = 0.0f;   // this thread's dimension-d accumulator
    float pnn = 0.0f;   // unnormalized e at the diagonal (replicated per thread)

    for (int m0 = 0; m0 < NNODES; m0 += 64) {
        const int m = m0 + d;
        const float* kr = kh + (long long)m * D;
        float s = 0.0f;
        #pragma unroll
        for (int j = 0; j < D; j++) s += qs[j] * kr[j];
        s = s * 0.125f + adjrow[m];  // scale = 1/sqrt(64)

        // chunk max
        red[d] = s;
        __syncthreads();
        #pragma unroll
        for (int off = 32; off > 0; off >>= 1) {
            if (d < off) red[d] = fmaxf(red[d], red[d + off]);
            __syncthreads();
        }
        const float m_new = fmaxf(m_run, red[0]);
        const float corr = expf(m_run - m_new);  // expf(-inf)=0 on first iter
        const float ev = expf(s - m_new);
        __syncthreads();  // everyone has read red[0]

        ebuf[d] = ev;
        red[d] = ev;
        if (m == n) pe_sh = ev;  // at most one thread, once over whole loop
        __syncthreads();
        #pragma unroll
        for (int off = 32; off > 0; off >>= 1) {
            if (d < off) red[d] += red[d + off];
            __syncthreads();
        }
        l_run = l_run * corr + red[0];

        const float pchunk = (m0 <= n && n < m0 + 64) ? pe_sh : 0.0f;
        pnn = pnn * corr + pchunk;

        acc *= corr;
        #pragma unroll 8
        for (int j = 0; j < 64; j++)
            acc += ebuf[j] * vh[(long long)(m0 + j) * D + d];
        __syncthreads();  // done reading ebuf/red/pe_sh
        if (d == 0) pe_sh = 0.0f;
        // next write to pe_sh/ebuf/red is after the next iteration's first
        // __syncthreads(), so ordering is safe.
    }

    m_run = m_run;  // (kept for clarity; not needed further)
    const float inv_l = 1.0f / l_run;
    out[base + d] = b * acc * inv_l + (a - b * pnn * inv_l) * v[base + d];
}

extern "C" void kernel_launch(void* const* d_in, const int* in_sizes, int n_in,
                              void* d_out, int out_size) {
    const float* q     = (const float*)d_in[0];
    const float* k     = (const float*)d_in[1];
    const float* v     = (const float*)d_in[2];
    const float* adj   = (const float*)d_in[3];
    const float* alpha = (const float*)d_in[4];
    const float* beta  = (const float*)d_in[5];
    float* out = (float*)d_out;

    dim3 grid(NNODES, H);
    attn_adj_kernel<<<grid, D>>>(q, k, v, adj, alpha, beta, out);
}

// round 5
// speedup vs baseline: 3.2791x; 3.2791x over previous
#include <cuda_runtime.h>
#include <math.h>

#define H 8
#define NNODES 4096
#define D 64
#define ROWS_PER_BLOCK 64   // rows of one head handled per block
#define GROUPS 4            // 4 row-groups of 64 threads in the general path

// out[h,n,:] = beta_h*(P@v)[n,:] + (alpha_h - beta_h*P[n,n]) * v[h,n,:]
// where P = softmax(q·K^T/8 + adj). When beta_h == 0 this is exactly
// out = alpha_h * v (softmax finite, 0*finite == 0 in fp32):
// the block takes a vectorized scaled-copy path.
__global__ __launch_bounds__(256) void attn_adj_kernel(
        const float* __restrict__ q,
        const float* __restrict__ k,
        const float* __restrict__ v,
        const float* __restrict__ adj,
        const float* __restrict__ alpha,
        const float* __restrict__ beta,
        float* __restrict__ out) {
    const int h  = blockIdx.y;
    const int r0 = blockIdx.x * ROWS_PER_BLOCK;
    const float a = alpha[h];
    const float b = beta[h];
    const long long blk_base = ((long long)h * NNODES + r0) * D;

    if (b == 0.0f) {
        // ---- fast path: out = alpha * v, 64 rows = 1024 float4 per block ----
        const float4* __restrict__ src = (const float4*)(v + blk_base);
        float4* __restrict__ dst = (float4*)(out + blk_base);
        const int t = threadIdx.x;
        float4 r[4];
        #pragma unroll
        for (int i = 0; i < 4; i++) r[i] = src[t + i * 256];   // MLP=4
        #pragma unroll
        for (int i = 0; i < 4; i++) {
            r[i].x *= a; r[i].y *= a; r[i].z *= a; r[i].w *= a;
            dst[t + i * 256] = r[i];
        }
        return;
    }

    // ---- general path: 4 rows in parallel (64 threads each), 16 passes ----
    const int g = threadIdx.x >> 6;   // row-group 0..3
    const int d = threadIdx.x & 63;   // dimension 0..63

    __shared__ float qs[GROUPS][D];
    __shared__ float ebuf[GROUPS][64];
    __shared__ float red[GROUPS][64];
    __shared__ float pe_sh[GROUPS];

    const float* kh = k + (long long)h * NNODES * D;
    const float* vh = v + (long long)h * NNODES * D;

    for (int it = 0; it < ROWS_PER_BLOCK / GROUPS; it++) {
        const int n = r0 + it * GROUPS + g;
        const long long base = ((long long)h * NNODES + n) * D;
        const float* adjrow = adj + ((long long)h * NNODES + n) * NNODES;

        qs[g][d] = q[base + d];
        if (d == 0) pe_sh[g] = 0.0f;
        __syncthreads();

        float m_run = -INFINITY;
        float l_run = 0.0f;
        float acc = 0.0f;   // this thread's dimension-d accumulator
        float pnn = 0.0f;   // unnormalized e at the diagonal

        for (int m0 = 0; m0 < NNODES; m0 += 64) {
            const int m = m0 + d;
            const float* kr = kh + (long long)m * D;
            float s = 0.0f;
            #pragma unroll
            for (int j = 0; j < D; j++) s += qs[g][j] * kr[j];
            s = s * 0.125f + adjrow[m];

            // chunk max (64-wide reduction within the group)
            red[g][d] = s;
            __syncthreads();
            #pragma unroll
            for (int off = 32; off > 0; off >>= 1) {
                if (d < off) red[g][d] = fmaxf(red[g][d], red[g][d + off]);
                __syncthreads();
            }
            const float m_new = fmaxf(m_run, red[g][0]);
            const float corr = expf(m_run - m_new);  // expf(-inf)=0 first iter
            const float ev = expf(s - m_new);
            __syncthreads();  // everyone done reading red[g][0]

            ebuf[g][d] = ev;
            red[g][d] = ev;
            if (m == n) pe_sh[g] = ev;   // at most once over the whole loop
            __syncthreads();
            #pragma unroll
            for (int off = 32; off > 0; off >>= 1) {
                if (d < off) red[g][d] += red[g][d + off];
                __syncthreads();
            }
            l_run = l_run * corr + red[g][0];

            const float pchunk = (m0 <= n && n < m0 + 64) ? pe_sh[g] : 0.0f;
            pnn = pnn * corr + pchunk;

            acc *= corr;
            #pragma unroll 8
            for (int j = 0; j < 64; j++)
                acc += ebuf[g][j] * vh[(long long)(m0 + j) * D + d];
            __syncthreads();  // done reading ebuf/red/pe_sh before next write
            if (d == 0) pe_sh[g] = 0.0f;
        }

        m_run = m_run;
        const float inv_l = 1.0f / l_run;
        out[base + d] = b * acc * inv_l + (a - b * pnn * inv_l) * v[base + d];
        __syncthreads();  // before qs[g] is overwritten next row-pass
    }
}

extern "C" void kernel_launch(void* const* d_in, const int* in_sizes, int n_in,
                              void* d_out, int out_size) {
    const float* q     = (const float*)d_in[0];
    const float* k     = (const float*)d_in[1];
    const float* v     = (const float*)d_in[2];
    const float* adj   = (const float*)d_in[3];
    const float* alpha = (const float*)d_in[4];
    const float* beta  = (const float*)d_in[5];
    float* out = (float*)d_out;

    dim3 grid(NNODES / ROWS_PER_BLOCK, H);   // (64, 8) = 512 blocks
    attn_adj_kernel<<<grid, 256>>>(q, k, v, adj, alpha, beta, out);
}

// round 8
// speedup vs baseline: 3.4058x; 1.0386x over previous
#include <cuda_runtime.h>
#include <math.h>

#define H 8
#define NNODES 4096
#define D 64
#define BLOCK_THREADS 128
#define ROWS_PER_BLOCK 32   // 128 threads * 4 float4 * 4 floats / 64 = 32 rows
#define GROUPS 2            // general path: 2 row-groups of 64 threads

// out[h,n,:] = beta_h*(P@v)[n,:] + (alpha_h - beta_h*P[n,n]) * v[h,n,:]
// where P = softmax(q·K^T/8 + adj). When beta_h == 0 this is exactly
// out = alpha_h * v (softmax finite, 0*finite == 0 in fp32), so the block
// takes a vectorized scaled-copy path. v loads are issued BEFORE the beta
// branch so the scalar-load latency overlaps the bulk loads.
__global__ __launch_bounds__(BLOCK_THREADS) void attn_adj_kernel(
        const float* __restrict__ q,
        const float* __restrict__ k,
        const float* __restrict__ v,
        const float* __restrict__ adj,
        const float* __restrict__ alpha,
        const float* __restrict__ beta,
        float* __restrict__ out) {
    const int h  = blockIdx.y;
    const int r0 = blockIdx.x * ROWS_PER_BLOCK;
    const long long blk_base = ((long long)h * NNODES + r0) * D;

    // ---- speculative bulk loads (always valid addresses; MLP=4 in flight) ----
    const float4* __restrict__ src = (const float4*)(v + blk_base);
    const int t = threadIdx.x;
    float4 r[4];
    #pragma unroll
    for (int i = 0; i < 4; i++) r[i] = src[t + i * BLOCK_THREADS];

    const float a = alpha[h];
    const float b = beta[h];

    if (b == 0.0f) {
        // ---- fast path: out = alpha * v ----
        float4* __restrict__ dst = (float4*)(out + blk_base);
        #pragma unroll
        for (int i = 0; i < 4; i++) {
            r[i].x *= a; r[i].y *= a; r[i].z *= a; r[i].w *= a;
            dst[t + i * BLOCK_THREADS] = r[i];
        }
        return;
    }

    // ---- general path: 2 rows in parallel (64 threads each), 16 passes ----
    const int g = t >> 6;   // row-group 0..1
    const int d = t & 63;   // dimension 0..63

    __shared__ float qs[GROUPS][D];
    __shared__ float ebuf[GROUPS][64];
    __shared__ float red[GROUPS][64];
    __shared__ float pe_sh[GROUPS];

    const float* kh = k + (long long)h * NNODES * D;
    const float* vh = v + (long long)h * NNODES * D;

    for (int it = 0; it < ROWS_PER_BLOCK / GROUPS; it++) {
        const int n = r0 + it * GROUPS + g;
        const long long base = ((long long)h * NNODES + n) * D;
        const float* adjrow = adj + ((long long)h * NNODES + n) * NNODES;

        qs[g][d] = q[base + d];
        if (d == 0) pe_sh[g] = 0.0f;
        __syncthreads();

        float m_run = -INFINITY;
        float l_run = 0.0f;
        float acc = 0.0f;   // this thread's dimension-d accumulator
        float pnn = 0.0f;   // unnormalized e at the diagonal

        for (int m0 = 0; m0 < NNODES; m0 += 64) {
            const int m = m0 + d;
            const float* kr = kh + (long long)m * D;
            float s = 0.0f;
            #pragma unroll
            for (int j = 0; j < D; j++) s += qs[g][j] * kr[j];
            s = s * 0.125f + adjrow[m];

            // chunk max (64-wide reduction within the group)
            red[g][d] = s;
            __syncthreads();
            #pragma unroll
            for (int off = 32; off > 0; off >>= 1) {
                if (d < off) red[g][d] = fmaxf(red[g][d], red[g][d + off]);
                __syncthreads();
            }
            const float m_new = fmaxf(m_run, red[g][0]);
            const float corr = expf(m_run - m_new);  // expf(-inf)=0 first iter
            const float ev = expf(s - m_new);
            __syncthreads();  // everyone done reading red[g][0]

            ebuf[g][d] = ev;
            red[g][d] = ev;
            if (m == n) pe_sh[g] = ev;   // at most once over the whole loop
            __syncthreads();
            #pragma unroll
            for (int off = 32; off > 0; off >>= 1) {
                if (d < off) red[g][d] += red[g][d + off];
                __syncthreads();
            }
            l_run = l_run * corr + red[g][0];

            const float pchunk = (m0 <= n && n < m0 + 64) ? pe_sh[g] : 0.0f;
            pnn = pnn * corr + pchunk;

            acc *= corr;
            #pragma unroll 8
            for (int j = 0; j < 64; j++)
                acc += ebuf[g][j] * vh[(long long)(m0 + j) * D + d];
            __syncthreads();  // done reading ebuf/red/pe_sh before next write
            if (d == 0) pe_sh[g] = 0.0f;
        }

        const float inv_l = 1.0f / l_run;
        out[base + d] = b * acc * inv_l + (a - b * pnn * inv_l) * v[base + d];
        __syncthreads();  // before qs[g] is overwritten next row-pass
    }
}

extern "C" void kernel_launch(void* const* d_in, const int* in_sizes, int n_in,
                              void* d_out, int out_size) {
    const float* q     = (const float*)d_in[0];
    const float* k     = (const float*)d_in[1];
    const float* v     = (const float*)d_in[2];
    const float* adj   = (const float*)d_in[3];
    const float* alpha = (const float*)d_in[4];
    const float* beta  = (const float*)d_in[5];
    float* out = (float*)d_out;

    dim3 grid(NNODES / ROWS_PER_BLOCK, H);   // (128, 8) = 1024 blocks
    attn_adj_kernel<<<grid, BLOCK_THREADS>>>(q, k, v, adj, alpha, beta, out);
}